// round 15
// baseline (speedup 1.0000x reference)
#include <cuda_runtime.h>
#include <cuda_bf16.h>

#define D_ 128
#define L_ 4096
#define K_ 4096
#define N_ 65536
#define NTILE 512            // main CTAs: 128 tokens each
#define NCHUNK 64            // 64 chunks of 64 codes
#define MARGIN 0.016f        // 2 * bf16 dot error bound (2^-7) + slop
#define LCAP 8192
#define L2CAP 1024

typedef unsigned long long u64;
typedef unsigned int u32;

// ---- scratch (static device globals; no allocation) ----
__device__ __align__(16) float g_xn[(size_t)N_ * D_];              // normalized x fp32 [tok][d]
__device__ __align__(16) __nv_bfloat16 g_xb[(size_t)N_ * D_];      // bf16 copy
__device__ __align__(16) float g_cbn[(size_t)K_ * D_];             // normalized cb fp32 [code][d]
__device__ __align__(16) __nv_bfloat16 g_cbb[(size_t)K_ * D_];     // bf16 copy
__device__ float g_blocksum[NTILE];
__device__ u32 g_count;

// ---- smem offsets. A prologue tile (32KB) overlaps the u32 list (32KB).
#define SA_OFF     0
#define LIST_OFF   0            // u32 x LCAP = 32768
#define SB_OFF     32768        // B 4-deep ring: 4 x 16384 = 65536
#define RMAX_OFF   98304        // float x 128
#define WIN_OFF    98816        // u64 x 128
#define LIST2_OFF  99840        // u32 x L2CAP = 4096
#define SCODE_OFF  103936       // int x 128
#define CNT_OFF    104448
#define CNT2_OFF   104452
#define FLAG_OFF   104456
#define LP_OFF     104464       // 4 warp loss partials
#define SMEM_MAIN  104960

// ---- helpers ----
__device__ __forceinline__ u32 smem_u32(const void* p) {
    return (u32)__cvta_generic_to_shared(p);
}
__device__ __forceinline__ void cp16(u32 dst, const void* src) {
    asm volatile("cp.async.cg.shared.global [%0], [%1], 16;" :: "r"(dst), "l"(src) : "memory");
}
__device__ __forceinline__ void cp_commit() { asm volatile("cp.async.commit_group;" ::: "memory"); }
__device__ __forceinline__ void cp_wait2()  { asm volatile("cp.async.wait_group 2;" ::: "memory"); }
__device__ __forceinline__ void cp_wait1()  { asm volatile("cp.async.wait_group 1;" ::: "memory"); }
__device__ __forceinline__ void cp_wait0()  { asm volatile("cp.async.wait_group 0;" ::: "memory"); }

__device__ __forceinline__ void ldsm4(u32& r0, u32& r1, u32& r2, u32& r3, u32 addr) {
    asm volatile("ldmatrix.sync.aligned.m8n8.x4.shared.b16 {%0,%1,%2,%3}, [%4];"
                 : "=r"(r0), "=r"(r1), "=r"(r2), "=r"(r3) : "r"(addr));
}
__device__ __forceinline__ void mma16816(float* c, const u32* a, u32 b0, u32 b1) {
    asm volatile(
        "mma.sync.aligned.m16n8k16.row.col.f32.bf16.bf16.f32 "
        "{%0,%1,%2,%3}, {%4,%5,%6,%7}, {%8,%9}, {%0,%1,%2,%3};"
        : "+f"(c[0]), "+f"(c[1]), "+f"(c[2]), "+f"(c[3])
        : "r"(a[0]), "r"(a[1]), "r"(a[2]), "r"(a[3]), "r"(b0), "r"(b1));
}

// monotonic float<->u32 order-preserving map
__device__ __forceinline__ u32 ford(u32 b) {
    return b ^ (((int)b >> 31) | 0x80000000u);
}
__device__ __forceinline__ float finv(u32 u) {
    u32 b = (u & 0x80000000u) ? (u ^ 0x80000000u) : ~u;
    return __uint_as_float(b);
}

// ================= kernel 1: prep =================
__global__ void prep_kernel(const float* __restrict__ x, const float* __restrict__ cb) {
    __shared__ float s[128][65];
    __shared__ float psum[4][64];
    __shared__ float sinv[64];
    int tid = threadIdx.x;
    int bid = blockIdx.x;
    if (bid == 0 && tid == 0) g_count = 0;

    if (bid < 512) {
        int wid = tid >> 5, lane = tid & 31;
        int row = bid * 8 + wid;
        float4 v = ((const float4*)(cb + (size_t)row * D_))[lane];
        float ss = v.x * v.x + v.y * v.y + v.z * v.z + v.w * v.w;
#pragma unroll
        for (int o = 16; o; o >>= 1) ss += __shfl_xor_sync(0xffffffffu, ss, o);
        float inv = 1.0f / fmaxf(sqrtf(ss), 1e-12f);
        float vv[4] = {v.x * inv, v.y * inv, v.z * inv, v.w * inv};
        ((float4*)(g_cbn + (size_t)row * D_))[lane] = make_float4(vv[0], vv[1], vv[2], vv[3]);
        int d0 = lane * 4;
#pragma unroll
        for (int j = 0; j < 4; j++)
            g_cbb[(size_t)row * D_ + d0 + j] = __float2bfloat16(vv[j]);
    } else {
        int xb = bid - 512;
        int b = xb >> 6;
        int l0 = (xb & 63) * 64;
        int lq = tid & 15, drow = tid >> 4;
#pragma unroll
        for (int it = 0; it < 8; it++) {
            int d = it * 16 + drow;
            float4 v = *(const float4*)(x + ((size_t)(b * D_ + d)) * L_ + l0 + lq * 4);
            s[d][lq * 4 + 0] = v.x;
            s[d][lq * 4 + 1] = v.y;
            s[d][lq * 4 + 2] = v.z;
            s[d][lq * 4 + 3] = v.w;
        }
        __syncthreads();
        int t = tid & 63, g = tid >> 6;
        float p = 0.f;
#pragma unroll
        for (int dd = 0; dd < 32; dd++) { float v = s[g * 32 + dd][t]; p += v * v; }
        psum[g][t] = p;
        __syncthreads();
        if (tid < 64) {
            float n = sqrtf(psum[0][tid] + psum[1][tid] + psum[2][tid] + psum[3][tid]);
            sinv[tid] = 1.0f / fmaxf(n, 1e-12f);
        }
        __syncthreads();
        size_t n0 = (size_t)xb * 64;
#pragma unroll
        for (int it = 0; it < 32; it++) {
            int e = it * 256 + tid;
            int tt = e >> 7, d = e & 127;
            float v = s[d][tt] * sinv[tt];
            size_t idx = (n0 + tt) * D_ + d;
            g_xn[idx] = v;
            g_xb[idx] = __float2bfloat16(v);
        }
    }
}

// ================= kernel 2: HMMA GEMM + candidate filter + exact rescore =================
// CTA = 128 tokens x full 4096 codes, 256 threads, 2 CTAs/SM.
// Warp tile 32 tokens x 32 codes (4 token-groups x 2 code-groups): per kk-step
// 2 ldsm4 feed 8 HMMA, halving B smem traffic vs the 16x64 tile.
__global__ __launch_bounds__(256, 2) void vq_hmma_kernel(float* __restrict__ out, int out_size) {
    extern __shared__ char sm[];
    u32 sb = smem_u32(sm);
    u32* list   = (u32*)(sm + LIST_OFF);
    float* rmax = (float*)(sm + RMAX_OFF);
    u64* winner = (u64*)(sm + WIN_OFF);
    u32* list2  = (u32*)(sm + LIST2_OFF);
    int* scode  = (int*)(sm + SCODE_OFF);
    u32* cnt    = (u32*)(sm + CNT_OFF);
    u32* cnt2   = (u32*)(sm + CNT2_OFF);

    int tid = threadIdx.x, wid = tid >> 5, lane = tid & 31;
    int wg = wid >> 1;              // token group 0..3 (32 tokens each)
    int cg = wid & 1;               // code group 0..1 (32 codes each)
    int bid = blockIdx.x;
    if (tid < 128) winner[tid] = 0ull;
    if (tid == 0) { *cnt = 0; *cnt2 = 0; }

    // ---- prologue: group0 = A tile (transient, overlaps list) + B chunk 0; group1 = B chunk 1
#pragma unroll
    for (int i = 0; i < 8; i++) {
        int e = i * 256 + tid;
        int r = e >> 4, c = e & 15;
        cp16(sb + SA_OFF + r * 256 + ((c ^ (r & 15)) * 16),
             (const char*)g_xb + ((size_t)(bid * 128 + r)) * 256 + c * 16);
    }
#pragma unroll
    for (int i = 0; i < 4; i++) {
        int e = i * 256 + tid;
        int r = e >> 4, c = e & 15;
        cp16(sb + SB_OFF + r * 256 + ((c ^ (r & 15)) * 16),
             (const char*)g_cbb + ((size_t)r) * 256 + c * 16);
    }
    cp_commit();
#pragma unroll
    for (int i = 0; i < 4; i++) {
        int e = i * 256 + tid;
        int r = e >> 4, c = e & 15;
        cp16(sb + SB_OFF + 16384 + r * 256 + ((c ^ (r & 15)) * 16),
             (const char*)g_cbb + ((size_t)(64 + r)) * 256 + c * 16);
    }
    cp_commit();
    cp_wait1();          // group0 (A + B0) done
    __syncthreads();

    // ---- A fragments -> registers (once): 2 m16 tiles of this warp's 32 tokens ----
    u32 a[2][8][4];
    {
        int ar = (lane & 7) + ((lane >> 3) & 1) * 8;
#pragma unroll
        for (int mt = 0; mt < 2; mt++) {
            int row = wg * 32 + mt * 16 + ar;
#pragma unroll
            for (int kk = 0; kk < 8; kk++) {
                int ac = 2 * kk + (lane >> 4);
                ldsm4(a[mt][kk][0], a[mt][kk][1], a[mt][kk][2], a[mt][kk][3],
                      sb + SA_OFF + row * 256 + ((ac ^ (row & 15)) * 16));
            }
        }
    }
    __syncthreads();    // A region reads done before list reuse

    float rm[2][2] = {{-2.f, -2.f}, {-2.f, -2.f}};   // [mt][row-half]
    int g4 = lane >> 2, q4 = lane & 3;
    int rowInPair = ((lane >> 4) << 3) + (lane & 7);   // 0..15
    int half = (lane >> 3) & 1;
    u32 bLane = (u32)(cg * 32 + rowInPair) * 256;      // this warp's code rows

    for (int ck = 0; ck < NCHUNK; ck++) {
        // prefetch chunk ck+2 into ring slot (ck+2)&3 == (ck-2)&3: not in use by any warp
        if (ck <= NCHUNK - 3) {
            u32 nb = sb + SB_OFF + ((ck + 2) & 3) * 16384;
#pragma unroll
            for (int i = 0; i < 4; i++) {
                int e = i * 256 + tid;
                int r = e >> 4, c = e & 15;
                cp16(nb + r * 256 + ((c ^ (r & 15)) * 16),
                     (const char*)g_cbb + ((size_t)((ck + 2) * 64 + r)) * 256 + c * 16);
            }
            cp_commit();
            cp_wait2();
        } else if (ck == NCHUNK - 2) {
            cp_wait1();
        } else {
            cp_wait0();
        }
        __syncthreads();         // chunk-ck data visible to all; skew bound = 1

        u32 bBase = sb + SB_OFF + (ck & 3) * 16384 + bLane;
        float acc[2][4][4];
#pragma unroll
        for (int mt = 0; mt < 2; mt++)
#pragma unroll
            for (int j = 0; j < 4; j++) {
                acc[mt][j][0] = 0.f; acc[mt][j][1] = 0.f;
                acc[mt][j][2] = 0.f; acc[mt][j][3] = 0.f;
            }

#pragma unroll
        for (int kk = 0; kk < 8; kk++) {
            u32 swz = ((u32)(2 * kk + half) ^ (u32)rowInPair) * 16;
            u32 b0, b1, b2, b3, b4, b5, b6, b7;
            ldsm4(b0, b1, b2, b3, bBase + swz);           // codes cg*32 + 0..15
            ldsm4(b4, b5, b6, b7, bBase + 4096 + swz);    // codes cg*32 + 16..31
            mma16816(acc[0][0], a[0][kk], b0, b1);
            mma16816(acc[0][1], a[0][kk], b2, b3);
            mma16816(acc[0][2], a[0][kk], b4, b5);
            mma16816(acc[0][3], a[0][kk], b6, b7);
            mma16816(acc[1][0], a[1][kk], b0, b1);
            mma16816(acc[1][1], a[1][kk], b2, b3);
            mma16816(acc[1][2], a[1][kk], b4, b5);
            mma16816(acc[1][3], a[1][kk], b6, b7);
        }

        // ---- epilogue: chunk max -> running max -> candidate append (ballot-gated) ----
        float m[2][2];
#pragma unroll
        for (int mt = 0; mt < 2; mt++) {
            float lo = acc[mt][0][0], hi = acc[mt][0][2];
#pragma unroll
            for (int j = 0; j < 4; j++) {
                lo = fmaxf(lo, fmaxf(acc[mt][j][0], acc[mt][j][1]));
                hi = fmaxf(hi, fmaxf(acc[mt][j][2], acc[mt][j][3]));
            }
            lo = fmaxf(lo, __shfl_xor_sync(0xffffffffu, lo, 1));
            lo = fmaxf(lo, __shfl_xor_sync(0xffffffffu, lo, 2));
            hi = fmaxf(hi, __shfl_xor_sync(0xffffffffu, hi, 1));
            hi = fmaxf(hi, __shfl_xor_sync(0xffffffffu, hi, 2));
            rm[mt][0] = fmaxf(rm[mt][0], lo);
            rm[mt][1] = fmaxf(rm[mt][1], hi);
            m[mt][0] = lo; m[mt][1] = hi;
        }
        float thr00 = rm[0][0] - MARGIN, thr01 = rm[0][1] - MARGIN;
        float thr10 = rm[1][0] - MARGIN, thr11 = rm[1][1] - MARGIN;

        u32 anyc = __ballot_sync(0xffffffffu,
            (m[0][0] >= thr00) || (m[0][1] >= thr01) ||
            (m[1][0] >= thr10) || (m[1][1] >= thr11));
        if (anyc) {
            int colb = ck * 64 + cg * 32 + q4 * 2;
#pragma unroll
            for (int mt = 0; mt < 2; mt++) {
                int tok0 = wg * 32 + mt * 16 + g4, tok1 = tok0 + 8;
                float t0 = (mt ? thr10 : thr00), t1 = (mt ? thr11 : thr01);
#pragma unroll
                for (int j = 0; j < 4; j++) {
                    int c0 = colb + j * 8, c1 = c0 + 1;
                    if (acc[mt][j][0] >= t0) {
                        u32 p = atomicAdd(cnt, 1u);
                        if (p < LCAP)
                            list[p] = ((ford(__float_as_uint(acc[mt][j][0])) >> 19) << 19) | (u32)(tok0 << 12) | c0;
                    }
                    if (acc[mt][j][1] >= t0) {
                        u32 p = atomicAdd(cnt, 1u);
                        if (p < LCAP)
                            list[p] = ((ford(__float_as_uint(acc[mt][j][1])) >> 19) << 19) | (u32)(tok0 << 12) | c1;
                    }
                    if (acc[mt][j][2] >= t1) {
                        u32 p = atomicAdd(cnt, 1u);
                        if (p < LCAP)
                            list[p] = ((ford(__float_as_uint(acc[mt][j][2])) >> 19) << 19) | (u32)(tok1 << 12) | c0;
                    }
                    if (acc[mt][j][3] >= t1) {
                        u32 p = atomicAdd(cnt, 1u);
                        if (p < LCAP)
                            list[p] = ((ford(__float_as_uint(acc[mt][j][3])) >> 19) << 19) | (u32)(tok1 << 12) | c1;
                    }
                }
            }
        }
    }

    // ---- final per-token max to smem (cg=0 and cg=1 cover same tokens: atomic-free
    //      two-step: cg0 writes, barrier, cg1 max-merges) ----
    if (cg == 0) {
#pragma unroll
        for (int mt = 0; mt < 2; mt++) {
            rmax[wg * 32 + mt * 16 + g4] = rm[mt][0];
            rmax[wg * 32 + mt * 16 + 8 + g4] = rm[mt][1];
        }
    }
    __syncthreads();
    if (cg == 1) {
#pragma unroll
        for (int mt = 0; mt < 2; mt++) {
            int r0 = wg * 32 + mt * 16 + g4;
            rmax[r0] = fmaxf(rmax[r0], rm[mt][0]);
            rmax[r0 + 8] = fmaxf(rmax[r0 + 8], rm[mt][1]);
        }
    }
    __syncthreads();

    // ---- filter shortlist against final max (quantized upper bound: superset) ----
    int c1n = min(*cnt, (u32)LCAP);
    for (int i = tid; i < c1n; i += 256) {
        u32 e = list[i];
        int tok = (int)((e >> 12) & 127);
        u32 fupper = (e & 0xFFF80000u) | 0x7FFFFu;
        u32 thrf = ford(__float_as_uint(rmax[tok] - MARGIN));
        if (fupper >= thrf) {
            u32 p = atomicAdd(cnt2, 1u);
            if (p < L2CAP) list2[p] = e & 0x7FFFFu;
        }
    }
    __syncthreads();

    // ---- exact fp32 rescore of survivors (one warp per entry) ----
    int c2n = min(*cnt2, (u32)L2CAP);
    for (int i = wid; i < c2n; i += 8) {
        u32 m = list2[i];
        int tok = m >> 12, code = m & 4095;
        float4 xv = ((const float4*)(g_xn + ((size_t)(bid * 128 + tok)) * D_))[lane];
        float4 cv = ((const float4*)(g_cbn + (size_t)code * D_))[lane];
        float d = xv.x * cv.x + xv.y * cv.y + xv.z * cv.z + xv.w * cv.w;
#pragma unroll
        for (int o = 16; o; o >>= 1) d += __shfl_xor_sync(0xffffffffu, d, o);
        if (lane == 0) {
            u64 key = ((u64)ford(__float_as_uint(d)) << 32) | (u32)(4095 - code);
            atomicMax(winner + tok, key);
        }
    }
    __syncthreads();

    // ---- loss partial ----
    if (tid < 128) {
        u64 k = winner[tid];
        rmax[tid] = finv((u32)(k >> 32));
        scode[tid] = 4095 - (int)(k & 0xFFFu);
    }
    __syncthreads();
    if (wid < 4) {
        float v = rmax[tid];
#pragma unroll
        for (int o = 16; o; o >>= 1) v += __shfl_down_sync(0xffffffffu, v, o);
        if (lane == 0) ((float*)(sm + LP_OFF))[wid] = v;
    }
    __syncthreads();
    if (tid == 0) {
        float* pp = (float*)(sm + LP_OFF);
        g_blocksum[bid] = (pp[0] + pp[1]) + (pp[2] + pp[3]);
    }

    // ---- output: token-major coalesced stores, codebook gathered via L1/L2 ----
    {
        int bq = bid >> 5;                 // 32 CTAs per batch entry
        int l0 = (bid & 31) * 128;
        float* obase = out + ((size_t)(bq * D_)) * L_ + l0;
#pragma unroll 4
        for (int it = 0; it < 64; it++) {
            int e = it * 256 + tid;
            int d = e >> 7, t = e & 127;
            obase[(size_t)d * L_ + t] = g_cbn[(size_t)scode[t] * D_ + d];
        }
    }

    // ---- last block finalizes loss ----
    int* flag = (int*)(sm + FLAG_OFF);
    if (tid == 0) {
        __threadfence();
        *flag = (atomicAdd(&g_count, 1u) == NTILE - 1);
    }
    __syncthreads();
    if (*flag) {
        __threadfence();
        float* red = (float*)(sm + SB_OFF);
        red[tid] = g_blocksum[tid] + g_blocksum[tid + 256];
        __syncthreads();
        for (int o = 128; o; o >>= 1) {
            if (tid < o) red[tid] += red[tid + o];
            __syncthreads();
        }
        if (tid == 0) out[out_size - 1] = 2.0f - 2.0f * red[0] / (float)N_;
    }
}

extern "C" void kernel_launch(void* const* d_in, const int* in_sizes, int n_in,
                              void* d_out, int out_size) {
    const float* x = (const float*)d_in[0];    // [16, 128, 4096] f32
    const float* cb = (const float*)d_in[1];   // [4096, 128] f32
    float* out = (float*)d_out;

    cudaFuncSetAttribute(vq_hmma_kernel,
                         cudaFuncAttributeMaxDynamicSharedMemorySize, SMEM_MAIN);

    prep_kernel<<<1536, 256>>>(x, cb);
    vq_hmma_kernel<<<NTILE, 256, SMEM_MAIN>>>(out, out_size);
}

// round 16
// speedup vs baseline: 1.1047x; 1.1047x over previous
#include <cuda_runtime.h>
#include <cuda_bf16.h>

#define D_ 128
#define L_ 4096
#define K_ 4096
#define N_ 65536
#define NTILE 1024           // main CTAs: 64 tokens each
#define NCHUNK 64            // 64 chunks of 64 codes
#define MARGIN 0.016f        // 2 * bf16 dot error bound (2^-7) + slop
#define LCAP 3072
#define L2CAP 512

typedef unsigned long long u64;
typedef unsigned int u32;

// ---- scratch (static device globals; no allocation) ----
__device__ __align__(16) float g_xn[(size_t)N_ * D_];              // normalized x fp32 [tok][d]
__device__ __align__(16) __nv_bfloat16 g_xb[(size_t)N_ * D_];      // bf16 copy
__device__ __align__(16) float g_cbn[(size_t)K_ * D_];             // normalized cb fp32 [code][d]
__device__ __align__(16) __nv_bfloat16 g_cbb[(size_t)K_ * D_];     // bf16 copy
__device__ float g_blocksum[NTILE];
__device__ u32 g_count;

// ---- smem offsets (per-CTA ~47.3KB -> 4 CTAs/SM) ----
#define LIST_OFF   0            // u32 x LCAP = 12288
#define SB_OFF     12288        // B 2-deep ring: 2 x 16384 = 32768
#define RMAX_OFF   45056        // float x 64
#define WIN_OFF    45312        // u64 x 64
#define LIST2_OFF  45824        // u32 x L2CAP = 2048
#define SCODE_OFF  47872        // int x 64
#define CNT_OFF    48128
#define CNT2_OFF   48132
#define FLAG_OFF   48136
#define LP_OFF     48144        // 2 warp loss partials
#define SMEM_MAIN  48384

// ---- helpers ----
__device__ __forceinline__ u32 smem_u32(const void* p) {
    return (u32)__cvta_generic_to_shared(p);
}
__device__ __forceinline__ void cp16(u32 dst, const void* src) {
    asm volatile("cp.async.cg.shared.global [%0], [%1], 16;" :: "r"(dst), "l"(src) : "memory");
}
__device__ __forceinline__ void cp_commit() { asm volatile("cp.async.commit_group;" ::: "memory"); }
__device__ __forceinline__ void cp_wait1()  { asm volatile("cp.async.wait_group 1;" ::: "memory"); }
__device__ __forceinline__ void cp_wait0()  { asm volatile("cp.async.wait_group 0;" ::: "memory"); }

__device__ __forceinline__ void ldsm4(u32& r0, u32& r1, u32& r2, u32& r3, u32 addr) {
    asm volatile("ldmatrix.sync.aligned.m8n8.x4.shared.b16 {%0,%1,%2,%3}, [%4];"
                 : "=r"(r0), "=r"(r1), "=r"(r2), "=r"(r3) : "r"(addr));
}
__device__ __forceinline__ void mma16816(float* c, const u32* a, u32 b0, u32 b1) {
    asm volatile(
        "mma.sync.aligned.m16n8k16.row.col.f32.bf16.bf16.f32 "
        "{%0,%1,%2,%3}, {%4,%5,%6,%7}, {%8,%9}, {%0,%1,%2,%3};"
        : "+f"(c[0]), "+f"(c[1]), "+f"(c[2]), "+f"(c[3])
        : "r"(a[0]), "r"(a[1]), "r"(a[2]), "r"(a[3]), "r"(b0), "r"(b1));
}

// monotonic float<->u32 order-preserving map
__device__ __forceinline__ u32 ford(u32 b) {
    return b ^ (((int)b >> 31) | 0x80000000u);
}
__device__ __forceinline__ float finv(u32 u) {
    u32 b = (u & 0x80000000u) ? (u ^ 0x80000000u) : ~u;
    return __uint_as_float(b);
}

// ================= kernel 1: prep =================
__global__ void prep_kernel(const float* __restrict__ x, const float* __restrict__ cb) {
    __shared__ float s[128][65];
    __shared__ float psum[4][64];
    __shared__ float sinv[64];
    int tid = threadIdx.x;
    int bid = blockIdx.x;
    if (bid == 0 && tid == 0) g_count = 0;

    if (bid < 512) {
        int wid = tid >> 5, lane = tid & 31;
        int row = bid * 8 + wid;
        float4 v = ((const float4*)(cb + (size_t)row * D_))[lane];
        float ss = v.x * v.x + v.y * v.y + v.z * v.z + v.w * v.w;
#pragma unroll
        for (int o = 16; o; o >>= 1) ss += __shfl_xor_sync(0xffffffffu, ss, o);
        float inv = 1.0f / fmaxf(sqrtf(ss), 1e-12f);
        float vv[4] = {v.x * inv, v.y * inv, v.z * inv, v.w * inv};
        ((float4*)(g_cbn + (size_t)row * D_))[lane] = make_float4(vv[0], vv[1], vv[2], vv[3]);
        int d0 = lane * 4;
#pragma unroll
        for (int j = 0; j < 4; j++)
            g_cbb[(size_t)row * D_ + d0 + j] = __float2bfloat16(vv[j]);
    } else {
        int xb = bid - 512;
        int b = xb >> 6;
        int l0 = (xb & 63) * 64;
        int lq = tid & 15, drow = tid >> 4;
#pragma unroll
        for (int it = 0; it < 8; it++) {
            int d = it * 16 + drow;
            float4 v = *(const float4*)(x + ((size_t)(b * D_ + d)) * L_ + l0 + lq * 4);
            s[d][lq * 4 + 0] = v.x;
            s[d][lq * 4 + 1] = v.y;
            s[d][lq * 4 + 2] = v.z;
            s[d][lq * 4 + 3] = v.w;
        }
        __syncthreads();
        int t = tid & 63, g = tid >> 6;
        float p = 0.f;
#pragma unroll
        for (int dd = 0; dd < 32; dd++) { float v = s[g * 32 + dd][t]; p += v * v; }
        psum[g][t] = p;
        __syncthreads();
        if (tid < 64) {
            float n = sqrtf(psum[0][tid] + psum[1][tid] + psum[2][tid] + psum[3][tid]);
            sinv[tid] = 1.0f / fmaxf(n, 1e-12f);
        }
        __syncthreads();
        size_t n0 = (size_t)xb * 64;
#pragma unroll
        for (int it = 0; it < 32; it++) {
            int e = it * 256 + tid;
            int tt = e >> 7, d = e & 127;
            float v = s[d][tt] * sinv[tt];
            size_t idx = (n0 + tt) * D_ + d;
            g_xn[idx] = v;
            g_xb[idx] = __float2bfloat16(v);
        }
    }
}

// ================= kernel 2: HMMA GEMM + candidate filter + exact rescore =================
// CTA = 64 tokens x full 4096 codes, 128 threads (4 warps), 4 CTAs/SM.
// Warp tile = 16 tokens x 64 codes (R12 mainloop). A fragments gathered
// directly from gmem (no A smem tile). B: 64-code chunks, 2-deep cp.async ring.
__global__ __launch_bounds__(128, 4) void vq_hmma_kernel(float* __restrict__ out, int out_size) {
    extern __shared__ char sm[];
    u32 sb = smem_u32(sm);
    u32* list   = (u32*)(sm + LIST_OFF);
    float* rmax = (float*)(sm + RMAX_OFF);
    u64* winner = (u64*)(sm + WIN_OFF);
    u32* list2  = (u32*)(sm + LIST2_OFF);
    int* scode  = (int*)(sm + SCODE_OFF);
    u32* cnt    = (u32*)(sm + CNT_OFF);
    u32* cnt2   = (u32*)(sm + CNT2_OFF);

    int tid = threadIdx.x, wid = tid >> 5, lane = tid & 31;
    int bid = blockIdx.x;
    if (tid < 64) winner[tid] = 0ull;
    if (tid == 0) { *cnt = 0; *cnt2 = 0; }

    // ---- B chunk 0 into ring buf 0 (8 cp16/thread) ----
#pragma unroll
    for (int i = 0; i < 8; i++) {
        int e = i * 128 + tid;
        int r = e >> 4, c = e & 15;
        cp16(sb + SB_OFF + r * 256 + ((c ^ (r & 15)) * 16),
             (const char*)g_cbb + ((size_t)r) * 256 + c * 16);
    }
    cp_commit();

    // ---- A fragments gathered directly from gmem (fragment-exact per-lane loads) ----
    // a[kk][0] = A[row0][16kk + (lane&3)*2 .. +1], a[kk][1] = A[row0+8][...],
    // a[kk][2] = A[row0][16kk+8 + ...],            a[kk][3] = A[row0+8][...]
    u32 a[8][4];
    {
        const char* base0 = (const char*)g_xb +
            ((size_t)(bid * 64 + wid * 16 + (lane >> 2))) * 256 + (lane & 3) * 4;
        const char* base8 = base0 + 8 * 256;
#pragma unroll
        for (int kk = 0; kk < 8; kk++) {
            a[kk][0] = *(const u32*)(base0 + kk * 32);
            a[kk][1] = *(const u32*)(base8 + kk * 32);
            a[kk][2] = *(const u32*)(base0 + kk * 32 + 16);
            a[kk][3] = *(const u32*)(base8 + kk * 32 + 16);
        }
    }

    float runmax0 = -2.0f, runmax1 = -2.0f;    // rows wid*16+g4 and +8
    int g4 = lane >> 2, q4 = lane & 3;
    int rowInPair = ((lane >> 4) << 3) + (lane & 7);   // 0..15
    int half = (lane >> 3) & 1;
    u32 bLane = rowInPair * 256;

    for (int ck = 0; ck < NCHUNK; ck++) {
        if (ck + 1 < NCHUNK) {
            u32 nb = sb + SB_OFF + ((ck + 1) & 1) * 16384;
#pragma unroll
            for (int i = 0; i < 8; i++) {
                int e = i * 128 + tid;
                int r = e >> 4, c = e & 15;
                cp16(nb + r * 256 + ((c ^ (r & 15)) * 16),
                     (const char*)g_cbb + ((size_t)((ck + 1) * 64 + r)) * 256 + c * 16);
            }
            cp_commit();
            cp_wait1();
        } else {
            cp_wait0();
        }
        __syncthreads();

        u32 bBase = sb + SB_OFF + (ck & 1) * 16384 + bLane;
        float acc[8][4];
#pragma unroll
        for (int j = 0; j < 8; j++) {
            acc[j][0] = 0.f; acc[j][1] = 0.f; acc[j][2] = 0.f; acc[j][3] = 0.f;
        }

#pragma unroll
        for (int kk = 0; kk < 8; kk++) {
            u32 swz = ((u32)(2 * kk + half) ^ (u32)rowInPair) * 16;
#pragma unroll
            for (int j0 = 0; j0 < 8; j0 += 2) {
                u32 b0, b1, b2, b3;
                ldsm4(b0, b1, b2, b3, bBase + j0 * 2048 + swz);
                mma16816(acc[j0], a[kk], b0, b1);
                mma16816(acc[j0 + 1], a[kk], b2, b3);
            }
        }

        // ---- epilogue: chunk max -> running max -> candidate append (ballot-gated) ----
        float m0 = acc[0][0], m1 = acc[0][2];
#pragma unroll
        for (int j = 0; j < 8; j++) {
            m0 = fmaxf(m0, fmaxf(acc[j][0], acc[j][1]));
            m1 = fmaxf(m1, fmaxf(acc[j][2], acc[j][3]));
        }
        m0 = fmaxf(m0, __shfl_xor_sync(0xffffffffu, m0, 1));
        m0 = fmaxf(m0, __shfl_xor_sync(0xffffffffu, m0, 2));
        m1 = fmaxf(m1, __shfl_xor_sync(0xffffffffu, m1, 1));
        m1 = fmaxf(m1, __shfl_xor_sync(0xffffffffu, m1, 2));
        runmax0 = fmaxf(runmax0, m0);
        runmax1 = fmaxf(runmax1, m1);
        float thr0 = runmax0 - MARGIN, thr1 = runmax1 - MARGIN;

        u32 anyc = __ballot_sync(0xffffffffu, (m0 >= thr0) || (m1 >= thr1));
        if (anyc) {
            int tok0 = wid * 16 + g4, tok1 = tok0 + 8;
            int colb = ck * 64 + q4 * 2;
#pragma unroll
            for (int j = 0; j < 8; j++) {
                int c0 = colb + j * 8, c1 = c0 + 1;
                if (acc[j][0] >= thr0) {
                    u32 p = atomicAdd(cnt, 1u);
                    if (p < LCAP)
                        list[p] = ((ford(__float_as_uint(acc[j][0])) >> 19) << 19) | (u32)(tok0 << 12) | c0;
                }
                if (acc[j][1] >= thr0) {
                    u32 p = atomicAdd(cnt, 1u);
                    if (p < LCAP)
                        list[p] = ((ford(__float_as_uint(acc[j][1])) >> 19) << 19) | (u32)(tok0 << 12) | c1;
                }
                if (acc[j][2] >= thr1) {
                    u32 p = atomicAdd(cnt, 1u);
                    if (p < LCAP)
                        list[p] = ((ford(__float_as_uint(acc[j][2])) >> 19) << 19) | (u32)(tok1 << 12) | c0;
                }
                if (acc[j][3] >= thr1) {
                    u32 p = atomicAdd(cnt, 1u);
                    if (p < LCAP)
                        list[p] = ((ford(__float_as_uint(acc[j][3])) >> 19) << 19) | (u32)(tok1 << 12) | c1;
                }
            }
        }
        __syncthreads();   // B-buf reads done before next prefetch overwrites
    }

    // ---- final per-token max to smem ----
    rmax[wid * 16 + g4] = runmax0;          // 4 lanes write identical value
    rmax[wid * 16 + 8 + g4] = runmax1;
    __syncthreads();

    // ---- filter shortlist against final max (quantized upper bound: superset) ----
    int c1n = min(*cnt, (u32)LCAP);
    for (int i = tid; i < c1n; i += 128) {
        u32 e = list[i];
        int tok = (int)((e >> 12) & 127);
        u32 fupper = (e & 0xFFF80000u) | 0x7FFFFu;
        u32 thrf = ford(__float_as_uint(rmax[tok] - MARGIN));
        if (fupper >= thrf) {
            u32 p = atomicAdd(cnt2, 1u);
            if (p < L2CAP) list2[p] = e & 0x7FFFFu;
        }
    }
    __syncthreads();

    // ---- exact fp32 rescore of survivors (one warp per entry) ----
    int c2n = min(*cnt2, (u32)L2CAP);
    for (int i = wid; i < c2n; i += 4) {
        u32 m = list2[i];
        int tok = m >> 12, code = m & 4095;
        float4 xv = ((const float4*)(g_xn + ((size_t)(bid * 64 + tok)) * D_))[lane];
        float4 cv = ((const float4*)(g_cbn + (size_t)code * D_))[lane];
        float d = xv.x * cv.x + xv.y * cv.y + xv.z * cv.z + xv.w * cv.w;
#pragma unroll
        for (int o = 16; o; o >>= 1) d += __shfl_xor_sync(0xffffffffu, d, o);
        if (lane == 0) {
            u64 key = ((u64)ford(__float_as_uint(d)) << 32) | (u32)(4095 - code);
            atomicMax(winner + tok, key);
        }
    }
    __syncthreads();

    // ---- loss partial ----
    if (tid < 64) {
        u64 k = winner[tid];
        rmax[tid] = finv((u32)(k >> 32));
        scode[tid] = 4095 - (int)(k & 0xFFFu);
    }
    __syncthreads();
    if (wid < 2) {
        float v = rmax[tid];
#pragma unroll
        for (int o = 16; o; o >>= 1) v += __shfl_down_sync(0xffffffffu, v, o);
        if (lane == 0) ((float*)(sm + LP_OFF))[wid] = v;
    }
    __syncthreads();
    if (tid == 0) {
        float* pp = (float*)(sm + LP_OFF);
        g_blocksum[bid] = pp[0] + pp[1];
    }

    // ---- output: token-major coalesced stores, codebook gathered via L1/L2 ----
    {
        int bq = bid >> 6;                 // 64 CTAs per batch entry
        int l0 = (bid & 63) * 64;
        float* obase = out + ((size_t)(bq * D_)) * L_ + l0;
#pragma unroll 4
        for (int it = 0; it < 64; it++) {
            int e = it * 128 + tid;
            int d = e >> 6, t = e & 63;
            obase[(size_t)d * L_ + t] = g_cbn[(size_t)scode[t] * D_ + d];
        }
    }

    // ---- last block finalizes loss ----
    int* flag = (int*)(sm + FLAG_OFF);
    if (tid == 0) {
        __threadfence();
        *flag = (atomicAdd(&g_count, 1u) == NTILE - 1);
    }
    __syncthreads();
    if (*flag) {
        __threadfence();
        float* red = (float*)(sm + SB_OFF);
        float sv = 0.f;
#pragma unroll
        for (int k = 0; k < 8; k++) sv += g_blocksum[tid + k * 128];
        red[tid] = sv;
        __syncthreads();
        for (int o = 64; o; o >>= 1) {
            if (tid < o) red[tid] += red[tid + o];
            __syncthreads();
        }
        if (tid == 0) out[out_size - 1] = 2.0f - 2.0f * red[0] / (float)N_;
    }
}

extern "C" void kernel_launch(void* const* d_in, const int* in_sizes, int n_in,
                              void* d_out, int out_size) {
    const float* x = (const float*)d_in[0];    // [16, 128, 4096] f32
    const float* cb = (const float*)d_in[1];   // [4096, 128] f32
    float* out = (float*)d_out;

    cudaFuncSetAttribute(vq_hmma_kernel,
                         cudaFuncAttributeMaxDynamicSharedMemorySize, SMEM_MAIN);

    prep_kernel<<<1536, 256>>>(x, cb);
    vq_hmma_kernel<<<NTILE, 128, SMEM_MAIN>>>(out, out_size);
}